// round 10
// baseline (speedup 1.0000x reference)
#include <cuda_runtime.h>
#include <math.h>
#include <stdint.h>

#define Tn 1024
#define Hn 1024
#define En 64
#define In 512
#define TWO_I 1024
#define Gn 8
#define EPG 8
#define TOPKG 4
#define TOPK 8
#define NV 65                 // 64 routed + 1 shared (virtual expert 64)

#define BM 64
#define BK 32
#define CF 1.00034f           // tf32-truncation bias correction for B operands

// ---------------- device scratch ----------------
__device__ int   g_counts[NV];
__device__ int   g_offsets[NV];
__device__ int   g_tokens[NV * Tn];
__device__ int   g_tk_e[Tn * TOPK];
__device__ int   g_tk_pos[Tn * TOPK];
__device__ float g_tk_w[Tn * TOPK];
__device__ float g_sc[Tn * En];
__device__ float g_ch[Tn * En];
__device__ float g_xr[(size_t)Tn * Hn];                  // x pre-rounded to tf32
__device__ float g_act[(size_t)(Tn * TOPK + Tn) * In];   // tf32 values
__device__ float g_down[(size_t)(Tn * TOPK + Tn) * Hn];

// ---------------- helpers ----------------
__device__ __forceinline__ unsigned f2tf(float f) {
    unsigned u;
    asm("cvt.rna.tf32.f32 %0, %1;" : "=r"(u) : "f"(f));
    return u;
}

__device__ __forceinline__ void mma_tf32(float* d, unsigned a0, unsigned a1,
                                         unsigned a2, unsigned a3,
                                         unsigned b0, unsigned b1) {
    asm volatile(
        "mma.sync.aligned.m16n8k8.row.col.f32.tf32.tf32.f32 "
        "{%0,%1,%2,%3}, {%4,%5,%6,%7}, {%8,%9}, {%0,%1,%2,%3};"
        : "+f"(d[0]), "+f"(d[1]), "+f"(d[2]), "+f"(d[3])
        : "r"(a0), "r"(a1), "r"(a2), "r"(a3), "r"(b0), "r"(b1));
}

__device__ __forceinline__ void cpa16(void* dst, const void* src) {
    unsigned d = (unsigned)__cvta_generic_to_shared(dst);
    asm volatile("cp.async.cg.shared.global [%0], [%1], 16;" :: "r"(d), "l"(src));
}
__device__ __forceinline__ void cpa16u(uint32_t dst, const void* src) {
    asm volatile("cp.async.cg.shared.global [%0], [%1], 16;" :: "r"(dst), "l"(src));
}
__device__ __forceinline__ void cpa_commit() { asm volatile("cp.async.commit_group;"); }
__device__ __forceinline__ void cpa_wait2()  { asm volatile("cp.async.wait_group 2;"); }
__device__ __forceinline__ void cpa_wait1()  { asm volatile("cp.async.wait_group 1;"); }
__device__ __forceinline__ void cpa_wait0()  { asm volatile("cp.async.wait_group 0;"); }

__device__ __forceinline__ uint32_t smem_u32(const void* p) {
    uint32_t a;
    asm("{ .reg .u64 t; cvta.to.shared.u64 t, %1; cvt.u32.u64 %0, t; }" : "=r"(a) : "l"(p));
    return a;
}

#define MBARRIER_INIT(mb, cnt) \
    asm volatile("mbarrier.init.shared.b64 [%0], %1;" :: "r"((uint32_t)(mb)), "r"((uint32_t)(cnt)) : "memory")
#define MBARRIER_ARRIVE(mb) \
    asm volatile("mbarrier.arrive.shared.b64 _, [%0];" :: "r"((uint32_t)(mb)) : "memory")
#define MBARRIER_WAIT_PARITY(mb, ph) do { \
    uint32_t _mb = (uint32_t)(mb), _ph = (uint32_t)(ph), _done; \
    asm volatile( \
        "{\n\t.reg .pred p;\n\t" \
        "mbarrier.try_wait.parity.acquire.cta.shared::cta.b64 p, [%1], %2;\n\t" \
        "selp.b32 %0, 1, 0, p;\n\t}" \
        : "=r"(_done) : "r"(_mb), "r"(_ph) : "memory"); \
    if (!_done) { \
        asm volatile( \
            "{\n\t.reg .pred P1;\n\t" \
            "WL_%=:\n\t" \
            "mbarrier.try_wait.parity.acquire.cta.shared::cta.b64 P1, [%0], %1, 0x989680;\n\t" \
            "@P1 bra.uni WD_%=;\n\t" \
            "bra.uni WL_%=;\n\t" \
            "WD_%=:\n\t}" \
            :: "r"(_mb), "r"(_ph) : "memory"); \
    } \
} while (0)

#define AS_P 36    // mod32==4: A frag conflict-free
#define BGP  136   // mod32==8: B frag conflict-free
#define BSP2 264   // mod32==8

// gemm1 warp-specialized geometry (floats)
#define G1_STAGEF 13312          // A 128x36=4608 + Bg 32x136=4352 + Bu 4352
#define G1_BG_OFF 4608
#define G1_BU_OFF 8960
#define G1_SMEMF (3 * G1_STAGEF + 128 + 16)   // stages + tok + mbarriers
#define G1_SMEMB (G1_SMEMF * 4)

// ---------------- kernel 0: prep (tf32 pre-round of x) + init ----------------
__global__ void k_prep(const float* __restrict__ x) {
    if (blockIdx.x == 0) {
        if (threadIdx.x < En) g_counts[threadIdx.x] = 0;
        if (threadIdx.x == En) g_counts[En] = Tn;
    }
    int i = blockIdx.x * 256 + threadIdx.x;
    float4 v = ((const float4*)x)[i];
    v.x = __uint_as_float(f2tf(v.x));
    v.y = __uint_as_float(f2tf(v.y));
    v.z = __uint_as_float(f2tf(v.z));
    v.w = __uint_as_float(f2tf(v.w));
    ((float4*)g_xr)[i] = v;
}

// ---------------- kernel 1a: routing logits ----------------
__global__ __launch_bounds__(256) void k_logits(const float* __restrict__ x,
                                                const float* __restrict__ gw,
                                                const float* __restrict__ eb) {
    __shared__ float4 sx[8][256];
    const int t0 = blockIdx.x * 8;
    const int tid = threadIdx.x;

    #pragma unroll
    for (int l = 0; l < 8; l++) {
        int idx = tid + l * 256;
        int tok = idx >> 8, c = idx & 255;
        sx[tok][c] = ((const float4*)(x + (size_t)(t0 + tok) * Hn))[c];
    }
    __syncthreads();

    const int e = tid >> 2, p = tid & 3;
    const float4* gr = (const float4*)(gw + (size_t)e * Hn);
    float acc[8];
    #pragma unroll
    for (int tok = 0; tok < 8; tok++) acc[tok] = 0.f;

    #pragma unroll 4
    for (int k = 0; k < 64; k++) {
        float4 g = gr[p + 4 * k];
        #pragma unroll
        for (int tok = 0; tok < 8; tok++) {
            float4 xv = sx[tok][p + 4 * k];
            acc[tok] += g.x * xv.x + g.y * xv.y + g.z * xv.z + g.w * xv.w;
        }
    }
    #pragma unroll
    for (int tok = 0; tok < 8; tok++) {
        acc[tok] += __shfl_xor_sync(0xffffffffu, acc[tok], 1);
        acc[tok] += __shfl_xor_sync(0xffffffffu, acc[tok], 2);
    }
    if (p == 0) {
        float b = eb[e];
        #pragma unroll
        for (int tok = 0; tok < 8; tok++) {
            float sc = 1.f / (1.f + expf(-acc[tok]));
            g_sc[(t0 + tok) * En + e] = sc;
            g_ch[(t0 + tok) * En + e] = sc + b;
        }
    }
}

// ---------------- kernel 1b: grouped top-k selection ----------------
__global__ __launch_bounds__(256) void k_topk() {
    __shared__ float s_sc[8][En];
    __shared__ float s_ch[8][En];
    const int w = threadIdx.x >> 5, lane = threadIdx.x & 31;
    const int t = blockIdx.x * 8 + w;

    s_sc[w][lane]      = g_sc[t * En + lane];
    s_sc[w][lane + 32] = g_sc[t * En + lane + 32];
    s_ch[w][lane]      = g_ch[t * En + lane];
    s_ch[w][lane + 32] = g_ch[t * En + lane + 32];
    __syncwarp();

    if (lane == 0) {
        g_tokens[En * Tn + t] = t;
        float gs[Gn];
        #pragma unroll
        for (int g = 0; g < Gn; g++) {
            float m1 = -1e38f, m2 = -1e38f;
            #pragma unroll
            for (int j = 0; j < EPG; j++) {
                float v = s_ch[w][g * EPG + j];
                if (v > m1) { m2 = m1; m1 = v; }
                else if (v > m2) { m2 = v; }
            }
            gs[g] = m1 + m2;
        }
        unsigned gsel = 0;
        #pragma unroll
        for (int it = 0; it < TOPKG; it++) {
            float best = -1e38f; int bi = 0;
            #pragma unroll
            for (int g = 0; g < Gn; g++)
                if (!((gsel >> g) & 1u) && gs[g] > best) { best = gs[g]; bi = g; }
            gsel |= 1u << bi;
        }
        unsigned long long taken = 0ull;
        int eidx[TOPK]; float ws[TOPK]; float wsum = 0.f;
        #pragma unroll
        for (int it = 0; it < TOPK; it++) {
            float best = -1e38f; int bi = 0;
            for (int ee = 0; ee < En; ee++) {
                if (((gsel >> (ee >> 3)) & 1u) && !((taken >> ee) & 1ull)) {
                    float v = s_ch[w][ee];
                    if (v > best) { best = v; bi = ee; }
                }
            }
            taken |= 1ull << bi;
            eidx[it] = bi; ws[it] = s_sc[w][bi]; wsum += s_sc[w][bi];
        }
        float scale = 1.0f / wsum;
        #pragma unroll
        for (int k = 0; k < TOPK; k++) {
            int ee = eidx[k];
            int pos = atomicAdd(&g_counts[ee], 1);
            g_tokens[ee * Tn + pos] = t;
            g_tk_e[t * TOPK + k]   = ee;
            g_tk_pos[t * TOPK + k] = pos;
            g_tk_w[t * TOPK + k]   = ws[k] * scale;
        }
    }
}

// ---------------- kernel 2: offsets ----------------
__global__ void k_scan() {
    __shared__ int s[NV];
    int tid = threadIdx.x;
    if (tid < NV) s[tid] = g_counts[tid];
    __syncthreads();
    if (tid == 0) {
        int off = 0;
        for (int e = 0; e < NV; e++) { g_offsets[e] = off; off += s[e]; }
    }
}

// ---------------- kernel 3: gate_up GEMM — warp-specialized tf32 ----------------
// 320 threads: warps 0-7 consumers (2m x 4n, warp 64M x 32N dual gate/up),
// warps 8-9 producers. BM=128, N = 128 gate + 128 up, BK=32, ring of 3 stages.
// No __syncthreads in the mainloop: mbarrier full/empty ring.
__global__ __launch_bounds__(320, 1) void k_gemm1(const float* __restrict__ wgu,
                                                  const float* __restrict__ shgu) {
    const int e = blockIdx.y;
    const int n_e = g_counts[e];
    const int nb = blockIdx.x & 3;
    const int mt = blockIdx.x >> 2;
    const int row0 = mt * 128;
    if (row0 >= n_e) return;
    const float* Bp = (e < En) ? (wgu + (size_t)e * Hn * TWO_I) : shgu;
    const int off_e = g_offsets[e];
    const int colg = nb * 128;

    extern __shared__ float smem[];
    float* stages = smem;
    int* s_tok = (int*)(smem + 3 * G1_STAGEF);
    const uint32_t mbar = smem_u32(smem + 3 * G1_STAGEF + 128);  // full[3], empty[3]
    const int tid = threadIdx.x;

    if (tid == 0) {
        #pragma unroll
        for (int i = 0; i < 3; i++) {
            MBARRIER_INIT(mbar + i * 8, 64);        // full: 64 producer threads
            MBARRIER_INIT(mbar + 24 + i * 8, 8);    // empty: 8 consumer warps
        }
    }
    if (tid < 128) {
        int ridx = row0 + tid; if (ridx > n_e - 1) ridx = n_e - 1;
        s_tok[tid] = g_tokens[e * Tn + ridx];
    }
    __syncthreads();

    const int KT = Hn / BK;  // 32

    if (tid >= 256) {
        // ---------------- producers ----------------
        const int p = tid - 256;                    // 0..63
        const int p0 = p >> 3, ac = (p & 7) * 4;    // A: rows p0+8l, float col ac
        const int k0 = p >> 5, nc = (p & 31) * 4;   // B: k rows k0+2lb, float col nc
        const uint32_t sb = smem_u32(smem);

        const float* abase[16];
        #pragma unroll
        for (int l = 0; l < 16; l++)
            abase[l] = g_xr + (size_t)s_tok[p0 + 8 * l] * Hn + ac;
        const float* bbase = Bp + (size_t)k0 * TWO_I + colg + nc;

        uint32_t adst[16], bgdst[16], budst[16];
        #pragma unroll
        for (int l = 0; l < 16; l++) {
            adst[l]  = sb + ((p0 + 8 * l) * AS_P + ac) * 4;
            bgdst[l] = sb + (G1_BG_OFF + (k0 + 2 * l) * BGP + nc) * 4;
            budst[l] = sb + (G1_BU_OFF + (k0 + 2 * l) * BGP + nc) * 4;
        }

        for (int s = 0; s < KT; s++) {
            const int ring = s % 3;
            if (s >= 3) MBARRIER_WAIT_PARITY(mbar + 24 + ring * 8, ((s / 3) - 1) & 1);
            const uint32_t st = (uint32_t)(ring * G1_STAGEF * 4);
            const int kk = s * BK;
            #pragma unroll
            for (int l = 0; l < 16; l++)
                cpa16u(adst[l] + st, abase[l] + kk);
            const float* bs = bbase + (size_t)kk * TWO_I;
            #pragma unroll
            for (int l = 0; l < 16; l++) {
                cpa16u(bgdst[l] + st, bs + (size_t)l * 2 * TWO_I);
                cpa16u(budst[l] + st, bs + (size_t)l * 2 * TWO_I + In);
            }
            cpa_commit();
            if (s >= 2) { cpa_wait2(); MBARRIER_ARRIVE(mbar + ((s - 2) % 3) * 8); }
        }
        cpa_wait1(); MBARRIER_ARRIVE(mbar + ((KT - 2) % 3) * 8);
        cpa_wait0(); MBARRIER_ARRIVE(mbar + ((KT - 1) % 3) * 8);
        return;
    }

    // ---------------- consumers ----------------
    const int w = tid >> 5, lane = tid & 31;
    const int wm = w & 1, wn = w >> 1;
    const int qr = lane >> 2, qc = lane & 3;

    float accG[4][4][4], accU[4][4][4];
    #pragma unroll
    for (int m = 0; m < 4; m++)
        #pragma unroll
        for (int n = 0; n < 4; n++)
            #pragma unroll
            for (int j = 0; j < 4; j++) { accG[m][n][j] = 0.f; accU[m][n][j] = 0.f; }

    for (int s = 0; s < KT; s++) {
        const int ring = s % 3;
        MBARRIER_WAIT_PARITY(mbar + ring * 8, (s / 3) & 1);
        const float* Ab  = stages + ring * G1_STAGEF;
        const float* Bgb = Ab + G1_BG_OFF;
        const float* Bub = Ab + G1_BU_OFF;
        #pragma unroll
        for (int ks = 0; ks < BK; ks += 8) {
            unsigned a[4][4];
            #pragma unroll
            for (int m = 0; m < 4; m++) {
                int r0 = wm * 64 + m * 16 + qr;
                a[m][0] = __float_as_uint(Ab[r0 * AS_P + ks + qc]);
                a[m][1] = __float_as_uint(Ab[(r0 + 8) * AS_P + ks + qc]);
                a[m][2] = __float_as_uint(Ab[r0 * AS_P + ks + qc + 4]);
                a[m][3] = __float_as_uint(Ab[(r0 + 8) * AS_P + ks + qc + 4]);
            }
            #pragma unroll
            for (int n = 0; n < 4; n++) {
                int c = wn * 32 + n * 8 + qr;
                unsigned bg0 = __float_as_uint(Bgb[(ks + qc) * BGP + c]);
                unsigned bg1 = __float_as_uint(Bgb[(ks + qc + 4) * BGP + c]);
                #pragma unroll
                for (int m = 0; m < 4; m++)
                    mma_tf32(accG[m][n], a[m][0], a[m][1], a[m][2], a[m][3], bg0, bg1);
                unsigned bu0 = __float_as_uint(Bub[(ks + qc) * BGP + c]);
                unsigned bu1 = __float_as_uint(Bub[(ks + qc + 4) * BGP + c]);
                #pragma unroll
                for (int m = 0; m < 4; m++)
                    mma_tf32(accU[m][n], a[m][0], a[m][1], a[m][2], a[m][3], bu0, bu1);
            }
        }
        __syncwarp();
        if (lane == 0) MBARRIER_ARRIVE(mbar + 24 + ring * 8);
    }

    // epilogue: bias-correct, silu(g)*u, tf32-round
    #pragma unroll
    for (int m = 0; m < 4; m++) {
        #pragma unroll
        for (int n = 0; n < 4; n++) {
            #pragma unroll
            for (int half_ = 0; half_ < 2; half_++) {
                int r = wm * 64 + m * 16 + qr + half_ * 8;
                int grow = row0 + r;
                if (grow < n_e) {
                    int c = colg + wn * 32 + n * 8 + qc * 2;
                    float gv0 = accG[m][n][half_ * 2 + 0] * CF;
                    float uv0 = accU[m][n][half_ * 2 + 0] * CF;
                    float gv1 = accG[m][n][half_ * 2 + 1] * CF;
                    float uv1 = accU[m][n][half_ * 2 + 1] * CF;
                    float o0 = gv0 / (1.f + expf(-gv0)) * uv0;
                    float o1 = gv1 / (1.f + expf(-gv1)) * uv1;
                    float2 o;
                    o.x = __uint_as_float(f2tf(o0));
                    o.y = __uint_as_float(f2tf(o1));
                    *(float2*)(g_act + (size_t)(off_e + grow) * In + c) = o;
                }
            }
        }
    }
}

// ---------------- kernel 4: down GEMM (tf32 raw-bit, unchanged) ----------------
__global__ __launch_bounds__(128, 2) void k_gemm2(const float* __restrict__ wd,
                                                  const float* __restrict__ shd) {
    const int e = blockIdx.y;
    const int n_e = g_counts[e];
    const int nb = blockIdx.x & 3;
    const int mt = blockIdx.x >> 2;
    const int row0 = mt * BM;
    if (row0 >= n_e) return;
    const float* Bp = (e < En) ? (wd + (size_t)e * In * Hn) : shd;
    const int off_e = g_offsets[e];
    const int colb = nb * 256;

    extern __shared__ float smem[];
    float* As = smem;
    float* Bs = smem + 2 * BM * AS_P;

    const int tid = threadIdx.x;

    const int ar = tid >> 3, ac = (tid & 7) * 4;
    const float* a_src[4];
    float* a_dst[4];
    #pragma unroll
    for (int l = 0; l < 4; l++) {
        int r = l * 16 + ar;
        int ridx = row0 + r; if (ridx > n_e - 1) ridx = n_e - 1;
        a_src[l] = g_act + (size_t)(off_e + ridx) * In + ac;
        a_dst[l] = As + r * AS_P + ac;
    }
    const int br = tid >> 6, bc = (tid & 63) * 4;
    const float* bss = Bp + (size_t)br * Hn + colb + bc;
    float* bsd = Bs + br * BSP2 + bc;

    const int wn = tid >> 5, lane = tid & 31;
    const int qr = lane >> 2, qc = lane & 3;
    const int abuf = BM * AS_P, bbuf = BK * BSP2;

    float acc[4][8][4];
    #pragma unroll
    for (int m = 0; m < 4; m++)
        #pragma unroll
        for (int n = 0; n < 8; n++)
            #pragma unroll
            for (int j = 0; j < 4; j++) acc[m][n][j] = 0.f;

    #pragma unroll
    for (int l = 0; l < 4; l++) cpa16(a_dst[l], a_src[l]);
    #pragma unroll
    for (int l = 0; l < 16; l++)
        cpa16(bsd + l * 2 * BSP2, bss + (size_t)l * 2 * Hn);
    cpa_commit();

    const int KT = In / BK;  // 16
    for (int kt = 0; kt < KT; kt++) {
        int buf = kt & 1;
        if (kt + 1 < KT) {
            int aoff = (buf ^ 1) ? abuf : 0;
            int boff = (buf ^ 1) ? bbuf : 0;
            size_t ka = (size_t)(kt + 1) * BK;
            #pragma unroll
            for (int l = 0; l < 4; l++) cpa16(a_dst[l] + aoff, a_src[l] + ka);
            #pragma unroll
            for (int l = 0; l < 16; l++)
                cpa16(bsd + boff + l * 2 * BSP2, bss + ka * Hn + (size_t)l * 2 * Hn);
            cpa_commit();
            cpa_wait1();
        } else {
            cpa_wait0();
        }
        __syncthreads();

        const float* Ab = As + buf * abuf;
        const float* Bb = Bs + buf * bbuf;
        #pragma unroll
        for (int ks = 0; ks < BK; ks += 8) {
            unsigned a[4][4];
            #pragma unroll
            for (int m = 0; m < 4; m++) {
                int r0 = m * 16 + qr;
                a[m][0] = __float_as_uint(Ab[r0 * AS_P + ks + qc]);
                a[m][1] = __float_as_uint(Ab[(r0 + 8) * AS_P + ks + qc]);
                a[m][2] = __float_as_uint(Ab[r0 * AS_P + ks + qc + 4]);
                a[m][3] = __float_as_uint(Ab[(r0 + 8) * AS_P + ks + qc + 4]);
            }
            #pragma unroll
            for (int n = 0; n < 8; n++) {
                int c = wn * 64 + n * 8 + qr;
                unsigned b0 = __float_as_uint(Bb[(ks + qc) * BSP2 + c]);
                unsigned b1 = __float_as_uint(Bb[(ks + qc + 4) * BSP2 + c]);
                #pragma unroll
                for (int m = 0; m < 4; m++)
                    mma_tf32(acc[m][n], a[m][0], a[m][1], a[m][2], a[m][3], b0, b1);
            }
        }
        __syncthreads();
    }

    #pragma unroll
    for (int m = 0; m < 4; m++) {
        #pragma unroll
        for (int n = 0; n < 8; n++) {
            #pragma unroll
            for (int half_ = 0; half_ < 2; half_++) {
                int r = m * 16 + qr + half_ * 8;
                int grow = row0 + r;
                if (grow < n_e) {
                    int c = colb + wn * 64 + n * 8 + qc * 2;
                    float2 o;
                    o.x = acc[m][n][half_ * 2 + 0] * CF;
                    o.y = acc[m][n][half_ * 2 + 1] * CF;
                    *(float2*)(g_down + (size_t)(off_e + grow) * Hn + c) = o;
                }
            }
        }
    }
}

// ---------------- kernel 5: weighted combine ----------------
__global__ void k_combine(float* __restrict__ out) {
    int t = blockIdx.x, tid = threadIdx.x;
    __shared__ int s_slot[9];
    __shared__ float s_w[9];
    if (tid < TOPK) {
        int ee = g_tk_e[t * TOPK + tid];
        s_slot[tid] = g_offsets[ee] + g_tk_pos[t * TOPK + tid];
        s_w[tid] = g_tk_w[t * TOPK + tid];
    } else if (tid == TOPK) {
        s_slot[8] = g_offsets[En] + t;
        s_w[8] = 1.f;
    }
    __syncthreads();
    int h = tid * 4;
    float4 acc = make_float4(0.f, 0.f, 0.f, 0.f);
    #pragma unroll
    for (int j = 0; j < 9; j++) {
        float4 v = *(const float4*)(g_down + (size_t)s_slot[j] * Hn + h);
        float wv = s_w[j];
        acc.x += wv * v.x; acc.y += wv * v.y;
        acc.z += wv * v.z; acc.w += wv * v.w;
    }
    *(float4*)(out + (size_t)t * Hn + h) = acc;
}

// ---------------- launch ----------------
extern "C" void kernel_launch(void* const* d_in, const int* in_sizes, int n_in,
                              void* d_out, int out_size) {
    const float* x    = (const float*)d_in[0];
    const float* gw   = (const float*)d_in[1];
    const float* eb   = (const float*)d_in[2];
    const float* wgu  = (const float*)d_in[3];
    const float* wd   = (const float*)d_in[4];
    const float* shgu = (const float*)d_in[5];
    const float* shd  = (const float*)d_in[6];
    float* out = (float*)d_out;

    const int smem2 = (2 * BM * AS_P + 2 * BK * BSP2) * 4;  // 86016 B
    cudaFuncSetAttribute(k_gemm1, cudaFuncAttributeMaxDynamicSharedMemorySize, G1_SMEMB);
    cudaFuncSetAttribute(k_gemm2, cudaFuncAttributeMaxDynamicSharedMemorySize, smem2);

    k_prep<<<Tn * Hn / 4 / 256, 256>>>(x);
    k_logits<<<Tn / 8, 256>>>(x, gw, eb);
    k_topk<<<Tn / 8, 256>>>();
    k_scan<<<1, 128>>>();
    k_gemm1<<<dim3(4 * 8, NV), 320, G1_SMEMB>>>(wgu, shgu);
    k_gemm2<<<dim3(16 * 4, NV), 128, smem2>>>(wd, shd);
    k_combine<<<Tn, 256>>>(out);
}

// round 12
// speedup vs baseline: 1.0781x; 1.0781x over previous
#include <cuda_runtime.h>
#include <math.h>

#define Tn 1024
#define Hn 1024
#define En 64
#define In 512
#define TWO_I 1024
#define Gn 8
#define EPG 8
#define TOPKG 4
#define TOPK 8
#define NV 65                 // 64 routed + 1 shared (virtual expert 64)

#define BM 64
#define BK 32
#define CF 1.00034f           // tf32-truncation bias correction for B operands

// ---------------- device scratch ----------------
__device__ int   g_counts[NV];
__device__ int   g_offsets[NV];
__device__ int   g_tokens[NV * Tn];
__device__ int   g_tk_e[Tn * TOPK];
__device__ int   g_tk_pos[Tn * TOPK];
__device__ float g_tk_w[Tn * TOPK];
__device__ float g_sc[Tn * En];
__device__ float g_ch[Tn * En];
__device__ float g_xr[(size_t)Tn * Hn];                  // x pre-rounded to tf32
__device__ float g_act[(size_t)(Tn * TOPK + Tn) * In];   // tf32 values
__device__ float g_down[(size_t)(Tn * TOPK + Tn) * Hn];

// ---------------- helpers ----------------
__device__ __forceinline__ unsigned f2tf(float f) {
    unsigned u;
    asm("cvt.rna.tf32.f32 %0, %1;" : "=r"(u) : "f"(f));
    return u;
}

__device__ __forceinline__ void mma_tf32(float* d, unsigned a0, unsigned a1,
                                         unsigned a2, unsigned a3,
                                         unsigned b0, unsigned b1) {
    asm volatile(
        "mma.sync.aligned.m16n8k8.row.col.f32.tf32.tf32.f32 "
        "{%0,%1,%2,%3}, {%4,%5,%6,%7}, {%8,%9}, {%0,%1,%2,%3};"
        : "+f"(d[0]), "+f"(d[1]), "+f"(d[2]), "+f"(d[3])
        : "r"(a0), "r"(a1), "r"(a2), "r"(a3), "r"(b0), "r"(b1));
}

__device__ __forceinline__ void cpa16(void* dst, const void* src) {
    unsigned d = (unsigned)__cvta_generic_to_shared(dst);
    asm volatile("cp.async.cg.shared.global [%0], [%1], 16;" :: "r"(d), "l"(src));
}
__device__ __forceinline__ void cpa_commit() { asm volatile("cp.async.commit_group;"); }
__device__ __forceinline__ void cpa_wait0()  { asm volatile("cp.async.wait_group 0;"); }

#define AS_P 36    // mod32==4: A frag conflict-free
#define BGP  136   // mod32==8: B frag conflict-free
#define BSP2 264   // mod32==8

// ---------------- kernel 0: prep (tf32 pre-round of x) + init ----------------
__global__ void k_prep(const float* __restrict__ x) {
    if (blockIdx.x == 0) {
        if (threadIdx.x < En) g_counts[threadIdx.x] = 0;
        if (threadIdx.x == En) g_counts[En] = Tn;
    }
    int i = blockIdx.x * 256 + threadIdx.x;
    float4 v = ((const float4*)x)[i];
    v.x = __uint_as_float(f2tf(v.x));
    v.y = __uint_as_float(f2tf(v.y));
    v.z = __uint_as_float(f2tf(v.z));
    v.w = __uint_as_float(f2tf(v.w));
    ((float4*)g_xr)[i] = v;
}

// ---------------- kernel 1a: routing logits ----------------
__global__ __launch_bounds__(256) void k_logits(const float* __restrict__ x,
                                                const float* __restrict__ gw,
                                                const float* __restrict__ eb) {
    __shared__ float4 sx[8][256];
    const int t0 = blockIdx.x * 8;
    const int tid = threadIdx.x;

    #pragma unroll
    for (int l = 0; l < 8; l++) {
        int idx = tid + l * 256;
        int tok = idx >> 8, c = idx & 255;
        sx[tok][c] = ((const float4*)(x + (size_t)(t0 + tok) * Hn))[c];
    }
    __syncthreads();

    const int e = tid >> 2, p = tid & 3;
    const float4* gr = (const float4*)(gw + (size_t)e * Hn);
    float acc[8];
    #pragma unroll
    for (int tok = 0; tok < 8; tok++) acc[tok] = 0.f;

    #pragma unroll 4
    for (int k = 0; k < 64; k++) {
        float4 g = gr[p + 4 * k];
        #pragma unroll
        for (int tok = 0; tok < 8; tok++) {
            float4 xv = sx[tok][p + 4 * k];
            acc[tok] += g.x * xv.x + g.y * xv.y + g.z * xv.z + g.w * xv.w;
        }
    }
    #pragma unroll
    for (int tok = 0; tok < 8; tok++) {
        acc[tok] += __shfl_xor_sync(0xffffffffu, acc[tok], 1);
        acc[tok] += __shfl_xor_sync(0xffffffffu, acc[tok], 2);
    }
    if (p == 0) {
        float b = eb[e];
        #pragma unroll
        for (int tok = 0; tok < 8; tok++) {
            float sc = 1.f / (1.f + expf(-acc[tok]));
            g_sc[(t0 + tok) * En + e] = sc;
            g_ch[(t0 + tok) * En + e] = sc + b;
        }
    }
}

// ---------------- kernel 1b: grouped top-k selection ----------------
__global__ __launch_bounds__(256) void k_topk() {
    __shared__ float s_sc[8][En];
    __shared__ float s_ch[8][En];
    const int w = threadIdx.x >> 5, lane = threadIdx.x & 31;
    const int t = blockIdx.x * 8 + w;

    s_sc[w][lane]      = g_sc[t * En + lane];
    s_sc[w][lane + 32] = g_sc[t * En + lane + 32];
    s_ch[w][lane]      = g_ch[t * En + lane];
    s_ch[w][lane + 32] = g_ch[t * En + lane + 32];
    __syncwarp();

    if (lane == 0) {
        g_tokens[En * Tn + t] = t;
        float gs[Gn];
        #pragma unroll
        for (int g = 0; g < Gn; g++) {
            float m1 = -1e38f, m2 = -1e38f;
            #pragma unroll
            for (int j = 0; j < EPG; j++) {
                float v = s_ch[w][g * EPG + j];
                if (v > m1) { m2 = m1; m1 = v; }
                else if (v > m2) { m2 = v; }
            }
            gs[g] = m1 + m2;
        }
        unsigned gsel = 0;
        #pragma unroll
        for (int it = 0; it < TOPKG; it++) {
            float best = -1e38f; int bi = 0;
            #pragma unroll
            for (int g = 0; g < Gn; g++)
                if (!((gsel >> g) & 1u) && gs[g] > best) { best = gs[g]; bi = g; }
            gsel |= 1u << bi;
        }
        unsigned long long taken = 0ull;
        int eidx[TOPK]; float ws[TOPK]; float wsum = 0.f;
        #pragma unroll
        for (int it = 0; it < TOPK; it++) {
            float best = -1e38f; int bi = 0;
            for (int ee = 0; ee < En; ee++) {
                if (((gsel >> (ee >> 3)) & 1u) && !((taken >> ee) & 1ull)) {
                    float v = s_ch[w][ee];
                    if (v > best) { best = v; bi = ee; }
                }
            }
            taken |= 1ull << bi;
            eidx[it] = bi; ws[it] = s_sc[w][bi]; wsum += s_sc[w][bi];
        }
        float scale = 1.0f / wsum;
        #pragma unroll
        for (int k = 0; k < TOPK; k++) {
            int ee = eidx[k];
            int pos = atomicAdd(&g_counts[ee], 1);
            g_tokens[ee * Tn + pos] = t;
            g_tk_e[t * TOPK + k]   = ee;
            g_tk_pos[t * TOPK + k] = pos;
            g_tk_w[t * TOPK + k]   = ws[k] * scale;
        }
    }
}

// ---------------- kernel 2: offsets ----------------
__global__ void k_scan() {
    __shared__ int s[NV];
    int tid = threadIdx.x;
    if (tid < NV) s[tid] = g_counts[tid];
    __syncthreads();
    if (tid == 0) {
        int off = 0;
        for (int e = 0; e < NV; e++) { g_offsets[e] = off; off += s[e]; }
    }
}

// ---------------- kernel 3: gate_up GEMM + SiLU*up (tf32, wait->sync->prefetch) --
// 128 threads, 4 warps in n. Block 64M x (128 gate + 128 up).
// Loop: wait0 (own stage kt); sync (globalize + overwrite fence);
//       prefetch(kt+1)->buf^1; compute(buf). One barrier per kt, correct.
__global__ __launch_bounds__(128, 2) void k_gemm1(const float* __restrict__ wgu,
                                                  const float* __restrict__ shgu) {
    const int e = blockIdx.y;
    const int n_e = g_counts[e];
    const int nb = blockIdx.x & 3;
    const int mt = blockIdx.x >> 2;
    const int row0 = mt * BM;
    if (row0 >= n_e) return;
    const float* Bp = (e < En) ? (wgu + (size_t)e * Hn * TWO_I) : shgu;
    const int off_e = g_offsets[e];
    const int colg = nb * 128;

    extern __shared__ float smem[];
    float* As = smem;                    // [2][64][AS_P]
    float* Bg = smem + 2 * BM * AS_P;    // [2][32][BGP]
    float* Bu = Bg + 2 * BK * BGP;       // [2][32][BGP]

    const int tid = threadIdx.x;

    const int ar = tid >> 3, ac = (tid & 7) * 4;
    const float* a_src[4];
    float* a_dst[4];
    #pragma unroll
    for (int l = 0; l < 4; l++) {
        int r = l * 16 + ar;
        int ridx = row0 + r; if (ridx > n_e - 1) ridx = n_e - 1;
        a_src[l] = g_xr + (size_t)g_tokens[e * Tn + ridx] * Hn + ac;
        a_dst[l] = As + r * AS_P + ac;
    }
    const int br = tid >> 5, bc = (tid & 31) * 4;
    const float* bgs = Bp + (size_t)br * TWO_I + colg + bc;
    const float* bus = bgs + In;
    float* bgd = Bg + br * BGP + bc;
    float* bud = Bu + br * BGP + bc;

    const int wn = tid >> 5, lane = tid & 31;
    const int qr = lane >> 2, qc = lane & 3;
    const int abuf = BM * AS_P, bbuf = BK * BGP;

    float accG[4][4][4], accU[4][4][4];
    #pragma unroll
    for (int m = 0; m < 4; m++)
        #pragma unroll
        for (int n = 0; n < 4; n++)
            #pragma unroll
            for (int j = 0; j < 4; j++) { accG[m][n][j] = 0.f; accU[m][n][j] = 0.f; }

    // prologue: stage 0 -> buf 0
    #pragma unroll
    for (int l = 0; l < 4; l++) cpa16(a_dst[l], a_src[l]);
    #pragma unroll
    for (int l = 0; l < 8; l++) {
        cpa16(bgd + l * 4 * BGP, bgs + (size_t)l * 4 * TWO_I);
        cpa16(bud + l * 4 * BGP, bus + (size_t)l * 4 * TWO_I);
    }
    cpa_commit();

    const int KT = Hn / BK;  // 32
    for (int kt = 0; kt < KT; kt++) {
        const int buf = kt & 1;
        cpa_wait0();       // own stage-kt copies retired
        __syncthreads();   // globalize stage-kt data; all warps past compute(kt-1)
        if (kt + 1 < KT) {
            const int aoff = (buf ^ 1) ? abuf : 0;
            const int boff = (buf ^ 1) ? bbuf : 0;
            const size_t ka = (size_t)(kt + 1) * BK;
            #pragma unroll
            for (int l = 0; l < 4; l++) cpa16(a_dst[l] + aoff, a_src[l] + ka);
            #pragma unroll
            for (int l = 0; l < 8; l++) {
                cpa16(bgd + boff + l * 4 * BGP, bgs + ka * TWO_I + (size_t)l * 4 * TWO_I);
                cpa16(bud + boff + l * 4 * BGP, bus + ka * TWO_I + (size_t)l * 4 * TWO_I);
            }
            cpa_commit();
        }

        const float* Ab = As + buf * abuf;
        const float* Bgb = Bg + buf * bbuf;
        const float* Bub = Bu + buf * bbuf;
        #pragma unroll
        for (int ks = 0; ks < BK; ks += 8) {
            unsigned a[4][4];
            #pragma unroll
            for (int m = 0; m < 4; m++) {
                int r0 = m * 16 + qr;
                a[m][0] = __float_as_uint(Ab[r0 * AS_P + ks + qc]);
                a[m][1] = __float_as_uint(Ab[(r0 + 8) * AS_P + ks + qc]);
                a[m][2] = __float_as_uint(Ab[r0 * AS_P + ks + qc + 4]);
                a[m][3] = __float_as_uint(Ab[(r0 + 8) * AS_P + ks + qc + 4]);
            }
            #pragma unroll
            for (int n = 0; n < 4; n++) {
                int c = wn * 32 + n * 8 + qr;
                unsigned bg0 = __float_as_uint(Bgb[(ks + qc) * BGP + c]);
                unsigned bg1 = __float_as_uint(Bgb[(ks + qc + 4) * BGP + c]);
                #pragma unroll
                for (int m = 0; m < 4; m++)
                    mma_tf32(accG[m][n], a[m][0], a[m][1], a[m][2], a[m][3], bg0, bg1);
                unsigned bu0 = __float_as_uint(Bub[(ks + qc) * BGP + c]);
                unsigned bu1 = __float_as_uint(Bub[(ks + qc + 4) * BGP + c]);
                #pragma unroll
                for (int m = 0; m < 4; m++)
                    mma_tf32(accU[m][n], a[m][0], a[m][1], a[m][2], a[m][3], bu0, bu1);
            }
        }
    }

    // epilogue: bias-correct, silu(g)*u, tf32-round (gemm2 A fed exact)
    #pragma unroll
    for (int m = 0; m < 4; m++) {
        #pragma unroll
        for (int n = 0; n < 4; n++) {
            #pragma unroll
            for (int half_ = 0; half_ < 2; half_++) {
                int r = m * 16 + qr + half_ * 8;
                int grow = row0 + r;
                if (grow < n_e) {
                    int c = colg + wn * 32 + n * 8 + qc * 2;
                    float gv0 = accG[m][n][half_ * 2 + 0] * CF;
                    float uv0 = accU[m][n][half_ * 2 + 0] * CF;
                    float gv1 = accG[m][n][half_ * 2 + 1] * CF;
                    float uv1 = accU[m][n][half_ * 2 + 1] * CF;
                    float o0 = gv0 / (1.f + expf(-gv0)) * uv0;
                    float o1 = gv1 / (1.f + expf(-gv1)) * uv1;
                    float2 o;
                    o.x = __uint_as_float(f2tf(o0));
                    o.y = __uint_as_float(f2tf(o1));
                    *(float2*)(g_act + (size_t)(off_e + grow) * In + c) = o;
                }
            }
        }
    }
}

// ---------------- kernel 4: down GEMM (tf32, wait->sync->prefetch) ----------------
__global__ __launch_bounds__(128, 2) void k_gemm2(const float* __restrict__ wd,
                                                  const float* __restrict__ shd) {
    const int e = blockIdx.y;
    const int n_e = g_counts[e];
    const int nb = blockIdx.x & 3;
    const int mt = blockIdx.x >> 2;
    const int row0 = mt * BM;
    if (row0 >= n_e) return;
    const float* Bp = (e < En) ? (wd + (size_t)e * In * Hn) : shd;
    const int off_e = g_offsets[e];
    const int colb = nb * 256;

    extern __shared__ float smem[];
    float* As = smem;                    // [2][64][AS_P]
    float* Bs = smem + 2 * BM * AS_P;    // [2][32][BSP2]

    const int tid = threadIdx.x;

    const int ar = tid >> 3, ac = (tid & 7) * 4;
    const float* a_src[4];
    float* a_dst[4];
    #pragma unroll
    for (int l = 0; l < 4; l++) {
        int r = l * 16 + ar;
        int ridx = row0 + r; if (ridx > n_e - 1) ridx = n_e - 1;
        a_src[l] = g_act + (size_t)(off_e + ridx) * In + ac;
        a_dst[l] = As + r * AS_P + ac;
    }
    const int br = tid >> 6, bc = (tid & 63) * 4;
    const float* bss = Bp + (size_t)br * Hn + colb + bc;
    float* bsd = Bs + br * BSP2 + bc;

    const int wn = tid >> 5, lane = tid & 31;
    const int qr = lane >> 2, qc = lane & 3;
    const int abuf = BM * AS_P, bbuf = BK * BSP2;

    float acc[4][8][4];
    #pragma unroll
    for (int m = 0; m < 4; m++)
        #pragma unroll
        for (int n = 0; n < 8; n++)
            #pragma unroll
            for (int j = 0; j < 4; j++) acc[m][n][j] = 0.f;

    #pragma unroll
    for (int l = 0; l < 4; l++) cpa16(a_dst[l], a_src[l]);
    #pragma unroll
    for (int l = 0; l < 16; l++)
        cpa16(bsd + l * 2 * BSP2, bss + (size_t)l * 2 * Hn);
    cpa_commit();

    const int KT = In / BK;  // 16
    for (int kt = 0; kt < KT; kt++) {
        const int buf = kt & 1;
        cpa_wait0();
        __syncthreads();
        if (kt + 1 < KT) {
            const int aoff = (buf ^ 1) ? abuf : 0;
            const int boff = (buf ^ 1) ? bbuf : 0;
            const size_t ka = (size_t)(kt + 1) * BK;
            #pragma unroll
            for (int l = 0; l < 4; l++) cpa16(a_dst[l] + aoff, a_src[l] + ka);
            #pragma unroll
            for (int l = 0; l < 16; l++)
                cpa16(bsd + boff + l * 2 * BSP2, bss + ka * Hn + (size_t)l * 2 * Hn);
            cpa_commit();
        }

        const float* Ab = As + buf * abuf;
        const float* Bb = Bs + buf * bbuf;
        #pragma unroll
        for (int ks = 0; ks < BK; ks += 8) {
            unsigned a[4][4];
            #pragma unroll
            for (int m = 0; m < 4; m++) {
                int r0 = m * 16 + qr;
                a[m][0] = __float_as_uint(Ab[r0 * AS_P + ks + qc]);
                a[m][1] = __float_as_uint(Ab[(r0 + 8) * AS_P + ks + qc]);
                a[m][2] = __float_as_uint(Ab[r0 * AS_P + ks + qc + 4]);
                a[m][3] = __float_as_uint(Ab[(r0 + 8) * AS_P + ks + qc + 4]);
            }
            #pragma unroll
            for (int n = 0; n < 8; n++) {
                int c = wn * 64 + n * 8 + qr;
                unsigned b0 = __float_as_uint(Bb[(ks + qc) * BSP2 + c]);
                unsigned b1 = __float_as_uint(Bb[(ks + qc + 4) * BSP2 + c]);
                #pragma unroll
                for (int m = 0; m < 4; m++)
                    mma_tf32(acc[m][n], a[m][0], a[m][1], a[m][2], a[m][3], b0, b1);
            }
        }
    }

    #pragma unroll
    for (int m = 0; m < 4; m++) {
        #pragma unroll
        for (int n = 0; n < 8; n++) {
            #pragma unroll
            for (int half_ = 0; half_ < 2; half_++) {
                int r = m * 16 + qr + half_ * 8;
                int grow = row0 + r;
                if (grow < n_e) {
                    int c = colb + wn * 64 + n * 8 + qc * 2;
                    float2 o;
                    o.x = acc[m][n][half_ * 2 + 0] * CF;
                    o.y = acc[m][n][half_ * 2 + 1] * CF;
                    *(float2*)(g_down + (size_t)(off_e + grow) * Hn + c) = o;
                }
            }
        }
    }
}

// ---------------- kernel 5: weighted combine ----------------
__global__ void k_combine(float* __restrict__ out) {
    int t = blockIdx.x, tid = threadIdx.x;
    __shared__ int s_slot[9];
    __shared__ float s_w[9];
    if (tid < TOPK) {
        int ee = g_tk_e[t * TOPK + tid];
        s_slot[tid] = g_offsets[ee] + g_tk_pos[t * TOPK + tid];
        s_w[tid] = g_tk_w[t * TOPK + tid];
    } else if (tid == TOPK) {
        s_slot[8] = g_offsets[En] + t;
        s_w[8] = 1.f;
    }
    __syncthreads();
    int h = tid * 4;
    float4 acc = make_float4(0.f, 0.f, 0.f, 0.f);
    #pragma unroll
    for (int j = 0; j < 9; j++) {
        float4 v = *(const float4*)(g_down + (size_t)s_slot[j] * Hn + h);
        float wv = s_w[j];
        acc.x += wv * v.x; acc.y += wv * v.y;
        acc.z += wv * v.z; acc.w += wv * v.w;
    }
    *(float4*)(out + (size_t)t * Hn + h) = acc;
}

// ---------------- launch ----------------
extern "C" void kernel_launch(void* const* d_in, const int* in_sizes, int n_in,
                              void* d_out, int out_size) {
    const float* x    = (const float*)d_in[0];
    const float* gw   = (const float*)d_in[1];
    const float* eb   = (const float*)d_in[2];
    const float* wgu  = (const float*)d_in[3];
    const float* wd   = (const float*)d_in[4];
    const float* shgu = (const float*)d_in[5];
    const float* shd  = (const float*)d_in[6];
    float* out = (float*)d_out;

    const int smem1 = (2 * BM * AS_P + 4 * BK * BGP) * 4;   // 88064 B
    const int smem2 = (2 * BM * AS_P + 2 * BK * BSP2) * 4;  // 86016 B
    cudaFuncSetAttribute(k_gemm1, cudaFuncAttributeMaxDynamicSharedMemorySize, smem1);
    cudaFuncSetAttribute(k_gemm2, cudaFuncAttributeMaxDynamicSharedMemorySize, smem2);

    k_prep<<<Tn * Hn / 4 / 256, 256>>>(x);
    k_logits<<<Tn / 8, 256>>>(x, gw, eb);
    k_topk<<<Tn / 8, 256>>>();
    k_scan<<<1, 128>>>();
    k_gemm1<<<dim3(16 * 4, NV), 128, smem1>>>(wgu, shgu);
    k_gemm2<<<dim3(16 * 4, NV), 128, smem2>>>(wd, shd);
    k_combine<<<Tn, 256>>>(out);
}